// round 14
// baseline (speedup 1.0000x reference)
#include <cuda_runtime.h>
#include <math.h>

// B=4, N=4096 (64x64), C=192, NH=3, HD=64
// branches: K_SPA {8,4,2} -> sides {57,61,63}, m {3249,3721,3969}
// rows per branch 4*m: {12996,14884,15876}; cum {0,12996,27880}; total 43756
#define SCALE_F 0.07216878364870323f
#define TOTROWS 43756

// ---------------- device scratch ----------------
__device__ float g_wtq [192*192];
__device__ float g_wtkv[192*192];
__device__ float g_wtnn[192*192];
__device__ float g_wc  [192*192*84];      // kk-major transposed conv weights (64+16+4 kk)
__device__ float g_q   [16384*192];       // q projection (B,N,C)
__device__ float g_t   [TOTROWS*192];     // sr-conv output then LN+GELU, [br][b][m][C]
__device__ float g_kv  [TOTROWS*128];     // k(0:64), v(64:128)
__device__ float g_v2  [TOTROWS*64];      // v + depthwise conv
__device__ float g_xcat[16384*192];       // concat of 3 attention outputs

// ---------------- weight transposes ----------------
__global__ void transpose_w(const float* __restrict__ w, float* __restrict__ wt,
                            int nout, int kin)
{
    int i = blockIdx.x * 256 + threadIdx.x;
    if (i < nout * kin) {
        int j = i / kin, k = i % kin;
        wt[k * nout + j] = w[i];
    }
}

// sr conv weights (co,ci,ky,kx) -> wc[(kk*192+ci)*192+co]
__global__ void conv_wt(const float* __restrict__ w, float* __restrict__ wt, int Ks)
{
    int total = 192 * 192 * Ks * Ks;
    int idx = blockIdx.x * 256 + threadIdx.x;
    if (idx >= total) return;
    int co  = idx / (192 * Ks * Ks);
    int rem = idx % (192 * Ks * Ks);
    int ci  = rem / (Ks * Ks);
    int kk  = rem % (Ks * Ks);
    wt[((size_t)kk * 192 + ci) * 192 + co] = w[idx];
}

// ---------------- GEMM 256x64 tile, BK=8, 8x8 microtile, double-buffered ----------------
__global__ void __launch_bounds__(256, 2) gemm256x64(
    const float* __restrict__ A, const float* __restrict__ Wt,
    const float* __restrict__ bias, float* __restrict__ Cm,
    int M, int K, int ldw, int ldc)
{
    __shared__ float As[2][8][260];
    __shared__ float Bs[2][8][68];
    int t = threadIdx.x;
    int rowBase = blockIdx.x * 256;
    int colBase = blockIdx.y * 64;
    int ty = t >> 3, tx = t & 7;
    int bk = t >> 4, bj = (t & 15) * 4;
    float acc[8][8] = {};

    int arow = rowBase + t; if (arow > M - 1) arow = M - 1;
    const float* ap = A + (size_t)arow * K;
    const float* bp = Wt + (size_t)bk * ldw + colBase + bj;

    {   // prologue: it = 0 into buf 0
        float4 a0v = *(const float4*)ap;
        float4 a1v = *(const float4*)(ap + 4);
        As[0][0][t] = a0v.x; As[0][1][t] = a0v.y; As[0][2][t] = a0v.z; As[0][3][t] = a0v.w;
        As[0][4][t] = a1v.x; As[0][5][t] = a1v.y; As[0][6][t] = a1v.z; As[0][7][t] = a1v.w;
        if (t < 128) *(float4*)&Bs[0][bk][bj] = *(const float4*)bp;
        ap += 8; bp += (size_t)8 * ldw;
    }
    int nk = K >> 3;
    for (int it = 0; it < nk; it++) {
        int cur = it & 1;
        __syncthreads();
        float4 na0, na1, nb;
        bool more = (it + 1 < nk);
        if (more) {
            na0 = *(const float4*)ap;
            na1 = *(const float4*)(ap + 4);
            if (t < 128) nb = *(const float4*)bp;
            ap += 8; bp += (size_t)8 * ldw;
        }
#pragma unroll
        for (int kk = 0; kk < 8; kk++) {
            float4 x0 = *(const float4*)&As[cur][kk][ty * 8];
            float4 x1 = *(const float4*)&As[cur][kk][ty * 8 + 4];
            float4 y0 = *(const float4*)&Bs[cur][kk][tx * 8];
            float4 y1 = *(const float4*)&Bs[cur][kk][tx * 8 + 4];
            float av[8] = {x0.x, x0.y, x0.z, x0.w, x1.x, x1.y, x1.z, x1.w};
            float bv[8] = {y0.x, y0.y, y0.z, y0.w, y1.x, y1.y, y1.z, y1.w};
#pragma unroll
            for (int i = 0; i < 8; i++)
#pragma unroll
                for (int j = 0; j < 8; j++)
                    acc[i][j] += av[i] * bv[j];
        }
        if (more) {
            int nxt = cur ^ 1;
            As[nxt][0][t] = na0.x; As[nxt][1][t] = na0.y; As[nxt][2][t] = na0.z; As[nxt][3][t] = na0.w;
            As[nxt][4][t] = na1.x; As[nxt][5][t] = na1.y; As[nxt][6][t] = na1.z; As[nxt][7][t] = na1.w;
            if (t < 128) *(float4*)&Bs[nxt][bk][bj] = nb;
        }
    }
#pragma unroll
    for (int i = 0; i < 8; i++) {
        int row = rowBase + ty * 8 + i;
        if (row < M) {
            int col = colBase + tx * 8;
            float4 o0, o1;
            o0.x = acc[i][0] + bias[col + 0]; o0.y = acc[i][1] + bias[col + 1];
            o0.z = acc[i][2] + bias[col + 2]; o0.w = acc[i][3] + bias[col + 3];
            o1.x = acc[i][4] + bias[col + 4]; o1.y = acc[i][5] + bias[col + 5];
            o1.z = acc[i][6] + bias[col + 6]; o1.w = acc[i][7] + bias[col + 7];
            *(float4*)&Cm[(size_t)row * ldc + col]     = o0;
            *(float4*)&Cm[(size_t)row * ldc + col + 4] = o1;
        }
    }
}

// ---------------- fat sr-conv: all 3 branches, implicit GEMM, double-buffered ----------------
// 1-D grid, heavy br0 (K=8) blocks enumerated FIRST so the 1536-iter critical-path
// blocks all start in wave 1; short br1/br2 blocks backfill the remaining slots.
// id layout: [0,156)   br0: ptile(13) x co(3) x b(4)
//            [156,336) br1: ptile(15) x co(3) x b(4)
//            [336,528) br2: ptile(16) x co(3) x b(4)
__global__ void __launch_bounds__(256, 2) conv_fat(
    const float* __restrict__ x, const float* __restrict__ wc,
    const float* __restrict__ bias0, const float* __restrict__ bias1,
    const float* __restrict__ bias2, float* __restrict__ tout)
{
    __shared__ float As[2][8][260];
    __shared__ float Bs[2][8][68];
    const int t = threadIdx.x;
    int id = blockIdx.x;
    const int KsA[3]    = {8, 4, 2};
    const int sideA[3]  = {57, 61, 63};
    const int mA[3]     = {3249, 3721, 3969};
    const int ntA[3]    = {13, 15, 16};
    const int idOffA[3] = {0, 156, 336};
    const int wcOffA[3] = {0, 64, 80};
    const int cumA[3]   = {0, 12996, 27880};
    int br = (id < 156) ? 0 : (id < 336 ? 1 : 2);
    int local = id - idOffA[br];
    int nt = ntA[br];
    int ptile = local % nt;
    int rest  = local / nt;
    int coBase = (rest % 3) * 64;
    int bb     = rest / 3;
    int Ks = KsA[br], side = sideA[br], m = mA[br];
    const float* bias = (br == 0) ? bias0 : (br == 1 ? bias1 : bias2);

    int p = ptile * 256 + t;
    int pc = (p < m) ? p : m - 1;
    int py = pc / side, px = pc - py * side;
    const float* xb  = x + (size_t)bb * 4096 * 192;
    const float* wcb = wc + (size_t)wcOffA[br] * 192 * 192;

    int ty = t >> 3, tx = t & 7;
    int bk = t >> 4, bj = (t & 15) * 4;
    float acc[8][8] = {};

    const float* anext = &xb[((size_t)(py * 64 + px)) * 192];
    const float* bnext = &wcb[(size_t)bk * 192 + coBase + bj];
    int nk = Ks * Ks * 24;

    {   // prologue it=0
        float4 a0v = *(const float4*)anext;
        float4 a1v = *(const float4*)(anext + 4);
        As[0][0][t] = a0v.x; As[0][1][t] = a0v.y; As[0][2][t] = a0v.z; As[0][3][t] = a0v.w;
        As[0][4][t] = a1v.x; As[0][5][t] = a1v.y; As[0][6][t] = a1v.z; As[0][7][t] = a1v.w;
        if (t < 128) *(float4*)&Bs[0][bk][bj] = *(const float4*)bnext;
    }
    // advance state to it=1
    int c24 = 1, kx = 0;
    anext += 8; bnext += 1536;

    for (int it = 0; it < nk; it++) {
        int cur = it & 1;
        __syncthreads();
        float4 na0, na1, nb;
        bool more = (it + 1 < nk);
        if (more) {
            na0 = *(const float4*)anext;
            na1 = *(const float4*)(anext + 4);
            if (t < 128) nb = *(const float4*)bnext;
            // advance to it+2
            c24++;
            if (c24 == 24) {
                c24 = 0; kx++;
                if (kx == Ks) { kx = 0; anext += (65 - Ks) * 192 - 184; }
                else anext += 8;
            } else anext += 8;
            bnext += 1536;
        }
#pragma unroll
        for (int kk = 0; kk < 8; kk++) {
            float4 x0 = *(const float4*)&As[cur][kk][ty * 8];
            float4 x1 = *(const float4*)&As[cur][kk][ty * 8 + 4];
            float4 y0 = *(const float4*)&Bs[cur][kk][tx * 8];
            float4 y1 = *(const float4*)&Bs[cur][kk][tx * 8 + 4];
            float av[8] = {x0.x, x0.y, x0.z, x0.w, x1.x, x1.y, x1.z, x1.w};
            float bv[8] = {y0.x, y0.y, y0.z, y0.w, y1.x, y1.y, y1.z, y1.w};
#pragma unroll
            for (int i = 0; i < 8; i++)
#pragma unroll
                for (int j = 0; j < 8; j++)
                    acc[i][j] += av[i] * bv[j];
        }
        if (more) {
            int nxt = cur ^ 1;
            As[nxt][0][t] = na0.x; As[nxt][1][t] = na0.y; As[nxt][2][t] = na0.z; As[nxt][3][t] = na0.w;
            As[nxt][4][t] = na1.x; As[nxt][5][t] = na1.y; As[nxt][6][t] = na1.z; As[nxt][7][t] = na1.w;
            if (t < 128) *(float4*)&Bs[nxt][bk][bj] = nb;
        }
    }
#pragma unroll
    for (int i = 0; i < 8; i++) {
        int pp = ptile * 256 + ty * 8 + i;
        if (pp < m) {
            size_t row = (size_t)cumA[br] + (size_t)bb * m + pp;
            int col = coBase + tx * 8;
            float4 o0, o1;
            o0.x = acc[i][0] + bias[col + 0]; o0.y = acc[i][1] + bias[col + 1];
            o0.z = acc[i][2] + bias[col + 2]; o0.w = acc[i][3] + bias[col + 3];
            o1.x = acc[i][4] + bias[col + 4]; o1.y = acc[i][5] + bias[col + 5];
            o1.z = acc[i][6] + bias[col + 6]; o1.w = acc[i][7] + bias[col + 7];
            *(float4*)&tout[row * 192 + col]     = o0;
            *(float4*)&tout[row * 192 + col + 4] = o1;
        }
    }
}

// ---------------- fat LayerNorm + exact GELU, in place, one warp per row ----------------
__global__ void ln_gelu_fat(float* __restrict__ tbuf,
                            const float* __restrict__ g0, const float* __restrict__ b0,
                            const float* __restrict__ g1, const float* __restrict__ b1,
                            const float* __restrict__ g2, const float* __restrict__ b2)
{
    int warp = threadIdx.x >> 5, lane = threadIdx.x & 31;
    int row = blockIdx.x * 8 + warp;
    if (row >= TOTROWS) return;
    const float* g; const float* bb;
    if (row < 12996)      { g = g0; bb = b0; }
    else if (row < 27880) { g = g1; bb = b1; }
    else                  { g = g2; bb = b2; }
    float* rp = tbuf + (size_t)row * 192;
    float v[6];
    float s = 0.f;
#pragma unroll
    for (int i = 0; i < 6; i++) { v[i] = rp[lane + i * 32]; s += v[i]; }
#pragma unroll
    for (int o = 16; o; o >>= 1) s += __shfl_xor_sync(0xffffffffu, s, o);
    float mean = s * (1.0f / 192.0f);
    float vs = 0.f;
#pragma unroll
    for (int i = 0; i < 6; i++) { float d = v[i] - mean; vs += d * d; }
#pragma unroll
    for (int o = 16; o; o >>= 1) vs += __shfl_xor_sync(0xffffffffu, vs, o);
    float inv = rsqrtf(vs * (1.0f / 192.0f) + 1e-5f);
#pragma unroll
    for (int i = 0; i < 6; i++) {
        int c = lane + i * 32;
        float y = (v[i] - mean) * inv * g[c] + bb[c];
        rp[c] = 0.5f * y * (1.0f + erff(y * 0.70710678118654752f));
    }
}

// ---------------- fat depthwise 3x3: v2 = v + dwconv(v) ----------------
__global__ void dw3x3_fat(const float* __restrict__ kv,
                          const float* __restrict__ w0, const float* __restrict__ c0,
                          const float* __restrict__ w1, const float* __restrict__ c1,
                          const float* __restrict__ w2, const float* __restrict__ c2,
                          float* __restrict__ v2)
{
    int idx = blockIdx.x * 256 + threadIdx.x;
    if (idx >= TOTROWS * 64) return;
    int d = idx & 63;
    int r = idx >> 6;
    int side, m, base;
    const float* w; const float* cb;
    if (r < 12996)      { side = 57; m = 3249; base = 0;     w = w0; cb = c0; }
    else if (r < 27880) { side = 61; m = 3721; base = 12996; w = w1; cb = c1; }
    else                { side = 63; m = 3969; base = 27880; w = w2; cb = c2; }
    int lr = r - base;
    int b = (lr >= 3 * m) ? 3 : (lr >= 2 * m) ? 2 : (lr >= m) ? 1 : 0;
    int p = lr - b * m;
    int y = p / side, xx = p - y * side;
    size_t rowb = (size_t)base + (size_t)b * m;
    float s = cb[d];
#pragma unroll
    for (int dy = 0; dy < 3; dy++) {
        int yy = y + dy - 1;
        if (yy < 0 || yy >= side) continue;
#pragma unroll
        for (int dx = 0; dx < 3; dx++) {
            int xc = xx + dx - 1;
            if (xc < 0 || xc >= side) continue;
            s += kv[(rowb + yy * side + xc) * 128 + 64 + d] * w[d * 9 + dy * 3 + dx];
        }
    }
    v2[idx] = kv[(rowb + p) * 128 + 64 + d] + s;
}

// ---------------- fat flash attention: 128 queries x 64 keys per tile ----------------
__global__ void __launch_bounds__(256) attn128(
    const float* __restrict__ qbuf, const float* __restrict__ kv,
    const float* __restrict__ v2, float* __restrict__ xcat)
{
    const int mA[3]   = {3249, 3721, 3969};
    const int cumA[3] = {0, 12996, 27880};
    extern __shared__ float smx[];
    float* Qst = smx;                  // [64 d][132]: Qst[d*132+q]
    float* Kst = Qst + 64 * 132;       // [64 d][68]:  Kst[d*68+k]
    float* Vs  = Kst + 64 * 68;        // [64 k][68]:  Vs[k*68+d]
    float* Ps  = Vs  + 64 * 68;        // [128 q][68]: Ps[q*68+k]
    __shared__ float corrs[128];
    __shared__ float sinv[128];

    int t = threadIdx.x;
    int b = blockIdx.y;
    int head = blockIdx.z;
    int m = mA[head];
    size_t kvBase = (size_t)cumA[head] + (size_t)b * m;
    int n0 = blockIdx.x * 128;
    int ty = t >> 4, tx = t & 15;      // rows ty*8.. (128), cols tx*4.. (64)
    int qrole = t >> 1, lane2 = t & 1;

    // load Q transposed (d-major)
    {
        int q = t >> 1;
        int dbase = (t & 1) * 32;
        const float* qp = &qbuf[((size_t)(b * 4096 + n0 + q)) * 192 + head * 64 + dbase];
#pragma unroll
        for (int r = 0; r < 8; r++) {
            float4 v = *(const float4*)&qp[r * 4];
            int d = dbase + r * 4;
            Qst[(d + 0) * 132 + q] = v.x; Qst[(d + 1) * 132 + q] = v.y;
            Qst[(d + 2) * 132 + q] = v.z; Qst[(d + 3) * 132 + q] = v.w;
        }
    }

    float Mi = -1e30f, Ssum = 0.0f;
    float acc[8][4] = {};
    int ntiles = (m + 63) >> 6;

    for (int kt = 0; kt < ntiles; kt++) {
        {   // load K (d-major) and V (k-major)
            int kr = t >> 2;
            int kidx = kt * 64 + kr;
            bool ok = (kidx < m);
            const float* krow = &kv[(kvBase + (ok ? kidx : 0)) * 128];
            const float* vrow = &v2[(kvBase + (ok ? kidx : 0)) * 64];
#pragma unroll
            for (int r = 0; r < 4; r++) {
                int d0 = (t & 3) * 16 + r * 4;
                float4 kq = ok ? *(const float4*)&krow[d0] : make_float4(0, 0, 0, 0);
                float4 vq = ok ? *(const float4*)&vrow[d0] : make_float4(0, 0, 0, 0);
                Kst[(d0 + 0) * 68 + kr] = kq.x; Kst[(d0 + 1) * 68 + kr] = kq.y;
                Kst[(d0 + 2) * 68 + kr] = kq.z; Kst[(d0 + 3) * 68 + kr] = kq.w;
                *(float4*)&Vs[kr * 68 + d0] = vq;
            }
        }
        __syncthreads();

        // QK: S[128][64], per-thread 8x4
        float s[8][4] = {};
#pragma unroll
        for (int dd = 0; dd < 64; dd++) {
            float4 a0 = *(const float4*)&Qst[dd * 132 + ty * 8];
            float4 a1 = *(const float4*)&Qst[dd * 132 + ty * 8 + 4];
            float4 bq = *(const float4*)&Kst[dd * 68 + tx * 4];
            float av[8] = {a0.x, a0.y, a0.z, a0.w, a1.x, a1.y, a1.z, a1.w};
            float bv[4] = {bq.x, bq.y, bq.z, bq.w};
#pragma unroll
            for (int i = 0; i < 8; i++)
#pragma unroll
                for (int j = 0; j < 4; j++)
                    s[i][j] += av[i] * bv[j];
        }
        {
            int kb = kt * 64 + tx * 4;
            float m0 = (kb + 0 < m) ? SCALE_F : 0.f;
            float m1 = (kb + 1 < m) ? SCALE_F : 0.f;
            float m2 = (kb + 2 < m) ? SCALE_F : 0.f;
            float m3 = (kb + 3 < m) ? SCALE_F : 0.f;
            float a0 = (kb + 0 < m) ? 0.f : -1e30f;
            float a1 = (kb + 1 < m) ? 0.f : -1e30f;
            float a2 = (kb + 2 < m) ? 0.f : -1e30f;
            float a3 = (kb + 3 < m) ? 0.f : -1e30f;
#pragma unroll
            for (int i = 0; i < 8; i++) {
                float4 o;
                o.x = s[i][0] * m0 + a0; o.y = s[i][1] * m1 + a1;
                o.z = s[i][2] * m2 + a2; o.w = s[i][3] * m3 + a3;
                *(float4*)&Ps[(ty * 8 + i) * 68 + tx * 4] = o;
            }
        }
        __syncthreads();

        // online softmax: 2 threads per query row, two passes over Ps
        {
            float* pr = &Ps[qrole * 68];
            float tm = -1e30f;
#pragma unroll
            for (int j = 0; j < 32; j++) tm = fmaxf(tm, pr[lane2 + 2 * j]);
            tm = fmaxf(tm, __shfl_xor_sync(0xffffffffu, tm, 1));
            float newM = fmaxf(Mi, tm);
            float corr = __expf(Mi - newM);
            float psum = 0.f;
#pragma unroll
            for (int j = 0; j < 32; j++) {
                float e = __expf(pr[lane2 + 2 * j] - newM);
                psum += e;
                pr[lane2 + 2 * j] = e;
            }
            Ssum = Ssum * corr + psum;
            Mi = newM;
            if (!lane2) corrs[qrole] = corr;
        }
        __syncthreads();

        // rescale + PV (k unrolled by 4 so P reads are float4)
        {
#pragma unroll
            for (int i = 0; i < 8; i++) {
                float cr = corrs[ty * 8 + i];
#pragma unroll
                for (int j = 0; j < 4; j++) acc[i][j] *= cr;
            }
#pragma unroll
            for (int k0 = 0; k0 < 64; k0 += 4) {
                float4 vv0 = *(const float4*)&Vs[(k0 + 0) * 68 + tx * 4];
                float4 vv1 = *(const float4*)&Vs[(k0 + 1) * 68 + tx * 4];
                float4 vv2 = *(const float4*)&Vs[(k0 + 2) * 68 + tx * 4];
                float4 vv3 = *(const float4*)&Vs[(k0 + 3) * 68 + tx * 4];
#pragma unroll
                for (int i = 0; i < 8; i++) {
                    float4 pf = *(const float4*)&Ps[(ty * 8 + i) * 68 + k0];
                    acc[i][0] += pf.x * vv0.x + pf.y * vv1.x + pf.z * vv2.x + pf.w * vv3.x;
                    acc[i][1] += pf.x * vv0.y + pf.y * vv1.y + pf.z * vv2.y + pf.w * vv3.y;
                    acc[i][2] += pf.x * vv0.z + pf.y * vv1.z + pf.z * vv2.z + pf.w * vv3.z;
                    acc[i][3] += pf.x * vv0.w + pf.y * vv1.w + pf.z * vv2.w + pf.w * vv3.w;
                }
            }
        }
        __syncthreads();
    }

    Ssum += __shfl_xor_sync(0xffffffffu, Ssum, 1);
    if (!lane2) sinv[qrole] = 1.0f / Ssum;
    __syncthreads();
#pragma unroll
    for (int i = 0; i < 8; i++) {
        int row = ty * 8 + i;
        float inv = sinv[row];
        float4 o;
        o.x = acc[i][0] * inv; o.y = acc[i][1] * inv;
        o.z = acc[i][2] * inv; o.w = acc[i][3] * inv;
        *(float4*)&xcat[((size_t)(b * 4096 + n0 + row)) * 192 + head * 64 + tx * 4] = o;
    }
}

// ---------------- launch ----------------
extern "C" void kernel_launch(void* const* d_in, const int* in_sizes, int n_in,
                              void* d_out, int out_size)
{
    (void)in_sizes; (void)n_in; (void)out_size;
    const float* x     = (const float*)d_in[0];
    const float* q_w   = (const float*)d_in[1];
    const float* q_b   = (const float*)d_in[2];
    const float* kv_w  = (const float*)d_in[3];
    const float* kv_b  = (const float*)d_in[4];
    const float* sr_w[3] = {(const float*)d_in[5], (const float*)d_in[7], (const float*)d_in[9]};
    const float* sr_b[3] = {(const float*)d_in[6], (const float*)d_in[8], (const float*)d_in[10]};
    const float* ln_g[3] = {(const float*)d_in[11], (const float*)d_in[13], (const float*)d_in[15]};
    const float* ln_b[3] = {(const float*)d_in[12], (const float*)d_in[14], (const float*)d_in[16]};
    const float* lc_w[3] = {(const float*)d_in[17], (const float*)d_in[19], (const float*)d_in[21]};
    const float* lc_b[3] = {(const float*)d_in[18], (const float*)d_in[20], (const float*)d_in[22]};
    const float* nn1_w = (const float*)d_in[23];
    const float* nn1_b = (const float*)d_in[24];
    float* out = (float*)d_out;

    float *p_wtq, *p_wtkv, *p_wtnn, *p_wc, *p_q, *p_t, *p_kv, *p_v2, *p_xcat;
    cudaGetSymbolAddress((void**)&p_wtq,  g_wtq);
    cudaGetSymbolAddress((void**)&p_wtkv, g_wtkv);
    cudaGetSymbolAddress((void**)&p_wtnn, g_wtnn);
    cudaGetSymbolAddress((void**)&p_wc,   g_wc);
    cudaGetSymbolAddress((void**)&p_q,    g_q);
    cudaGetSymbolAddress((void**)&p_t,    g_t);
    cudaGetSymbolAddress((void**)&p_kv,   g_kv);
    cudaGetSymbolAddress((void**)&p_v2,   g_v2);
    cudaGetSymbolAddress((void**)&p_xcat, g_xcat);

    int smem_attn = (64 * 132 + 64 * 68 + 64 * 68 + 128 * 68) * 4;
    cudaFuncSetAttribute(attn128, cudaFuncAttributeMaxDynamicSharedMemorySize, smem_attn);

    // weight prep
    transpose_w<<<(192 * 192 + 255) / 256, 256>>>(q_w,   p_wtq,  192, 192);
    transpose_w<<<(192 * 192 + 255) / 256, 256>>>(kv_w,  p_wtkv, 192, 192);
    transpose_w<<<(192 * 192 + 255) / 256, 256>>>(nn1_w, p_wtnn, 192, 192);
    conv_wt<<<(192 * 192 * 64 + 255) / 256, 256>>>(sr_w[0], p_wc,                 8);
    conv_wt<<<(192 * 192 * 16 + 255) / 256, 256>>>(sr_w[1], p_wc + 64 * 192 * 192, 4);
    conv_wt<<<(192 * 192 *  4 + 255) / 256, 256>>>(sr_w[2], p_wc + 80 * 192 * 192, 2);

    // q projection: (16384 x 192) @ (192 x 192)
    gemm256x64<<<dim3(64, 3), 256>>>(x, p_wtq, q_b, p_q, 16384, 192, 192, 192);

    // all 3 sr convs in one fat kernel, heavy-blocks-first 1-D grid
    conv_fat<<<528, 256>>>(x, p_wc, sr_b[0], sr_b[1], sr_b[2], p_t);

    // LN + GELU over all branches
    ln_gelu_fat<<<(TOTROWS + 7) / 8, 256>>>(p_t, ln_g[0], ln_b[0], ln_g[1], ln_b[1], ln_g[2], ln_b[2]);

    // kv projection for all branches: (43756 x 192) @ (192 x 128)
    gemm256x64<<<dim3((TOTROWS + 255) / 256, 2), 256>>>(p_t, p_wtkv, kv_b, p_kv, TOTROWS, 192, 192, 128);

    // depthwise conv on v
    dw3x3_fat<<<(TOTROWS * 64 + 255) / 256, 256>>>(p_kv, lc_w[0], lc_b[0], lc_w[1], lc_b[1],
                                                   lc_w[2], lc_b[2], p_v2);

    // fat attention: (qtile, batch, head)
    attn128<<<dim3(32, 4, 3), 256, smem_attn>>>(p_q, p_kv, p_v2, p_xcat);

    // final projection
    gemm256x64<<<dim3(64, 3), 256>>>(p_xcat, p_wtnn, nn1_b, out, 16384, 192, 192, 192);
}